// round 5
// baseline (speedup 1.0000x reference)
#include <cuda_runtime.h>
#include <math.h>

// ---------------------------------------------------------------------------
// QRNN: h_t = tanh(x_t @ Wh + b + h_{t-1} @ Uh),  T=512, B=32, D=1024
// Phase B: fp32 SGEMM (R3-proven version).
// Phase C: persistent recurrence, 128 CTAs = 32 ntiles x 4 batch-groups,
//          full-K per lane (no cross-warp reduce), per-warp release,
//          one __syncthreads per step, hs parity double-buffered.
// ---------------------------------------------------------------------------

#define TT 512
#define BB 32
#define DD 1024
#define QQ 256

#define HST 1028          // hs row stride (floats)
#define UCT 1036          // Usct column stride (floats)

__device__ float g_Wh[DD * DD];
__device__ float g_Uh[DD * DD];
__device__ int   g_cnt[TT][4];       // per (t, batch-group) warp counter

// ------------------------- sync primitives ----------------------------------
__device__ __forceinline__ int ld_acq(const int* p) {
    int v;
    asm volatile("ld.acquire.gpu.global.s32 %0, [%1];" : "=r"(v) : "l"(p) : "memory");
    return v;
}
__device__ __forceinline__ void red_add_rel(int* p, int v) {
    asm volatile("red.release.gpu.global.add.s32 [%0], %1;" :: "l"(p), "r"(v) : "memory");
}
__device__ __forceinline__ void spin_until(const int* p, int target) {
    while (ld_acq(p) < target) { }
}

// --------------------------- flag reset -------------------------------------
__global__ void zero_flags_kernel() {
    int i = blockIdx.x * blockDim.x + threadIdx.x;
    if (i < TT * 4) (&g_cnt[0][0])[i] = 0;
}

// --------------------------- quaternion matrix build ------------------------
__global__ void build_qmat_kernel(const float* __restrict__ wr,
                                  const float* __restrict__ wi,
                                  const float* __restrict__ wj,
                                  const float* __restrict__ wk,
                                  int which) {
    int e = blockIdx.x * blockDim.x + threadIdx.x;
    int d = blockIdx.y;
    int br = d >> 8, bc = e >> 8;
    int r = d & 255, c = e & 255;
    int comp = br ^ bc;
    int mask = (0x5390 >> (br * 4)) & 0xF;
    float s = ((mask >> bc) & 1) ? -1.0f : 1.0f;
    const float* w = (comp == 0) ? wr : (comp == 1) ? wi : (comp == 2) ? wj : wk;
    float* W = which ? g_Uh : g_Wh;
    W[d * DD + e] = s * w[r * QQ + c];
}

// --------------------------- fp32 SGEMM (R3 version) ------------------------
#define GBM 128
#define GBN 128
#define GBK 8

__global__ void __launch_bounds__(256)
sgemm_bias_kernel(const float* __restrict__ A, const float* __restrict__ bias,
                  float* __restrict__ C, int M, int N, int K) {
    __shared__ float As[2][GBK][GBM];
    __shared__ float Bs[2][GBK][GBN];
    const float* Bmat = g_Wh;

    int tid  = threadIdx.x;
    int brow = blockIdx.y, bcol = blockIdx.x;
    int arow = tid >> 1,  acol = (tid & 1) << 2;
    int brl  = tid >> 5,  bcl  = (tid & 31) << 2;

    const float* Ab = A + (size_t)(brow * GBM) * K;
    const float* Bb = Bmat + bcol * GBN;

    float4 av = *(const float4*)&Ab[(size_t)arow * K + acol];
    float4 bv = *(const float4*)&Bb[(size_t)brl * N + bcl];
    As[0][acol + 0][arow] = av.x;
    As[0][acol + 1][arow] = av.y;
    As[0][acol + 2][arow] = av.z;
    As[0][acol + 3][arow] = av.w;
    *(float4*)&Bs[0][brl][bcl] = bv;
    __syncthreads();

    int tm = (tid >> 4) << 3;
    int tn = (tid & 15) << 3;
    float acc[8][8];
#pragma unroll
    for (int i = 0; i < 8; i++)
#pragma unroll
        for (int j = 0; j < 8; j++) acc[i][j] = 0.0f;

    int nk = K / GBK;
    for (int kt = 0; kt < nk; ++kt) {
        int cur = kt & 1;
        float4 an, bn;
        if (kt + 1 < nk) {
            an = *(const float4*)&Ab[(size_t)arow * K + (kt + 1) * GBK + acol];
            bn = *(const float4*)&Bb[(size_t)((kt + 1) * GBK + brl) * N + bcl];
        }
#pragma unroll
        for (int kk = 0; kk < GBK; kk++) {
            float ra[8], rb[8];
            *(float4*)&ra[0] = *(const float4*)&As[cur][kk][tm];
            *(float4*)&ra[4] = *(const float4*)&As[cur][kk][tm + 4];
            *(float4*)&rb[0] = *(const float4*)&Bs[cur][kk][tn];
            *(float4*)&rb[4] = *(const float4*)&Bs[cur][kk][tn + 4];
#pragma unroll
            for (int i = 0; i < 8; i++)
#pragma unroll
                for (int j = 0; j < 8; j++) acc[i][j] += ra[i] * rb[j];
        }
        if (kt + 1 < nk) {
            int nxt = cur ^ 1;
            As[nxt][acol + 0][arow] = an.x;
            As[nxt][acol + 1][arow] = an.y;
            As[nxt][acol + 2][arow] = an.z;
            As[nxt][acol + 3][arow] = an.w;
            *(float4*)&Bs[nxt][brl][bcl] = bn;
            __syncthreads();
        }
    }

    float bias_r[8];
#pragma unroll
    for (int j = 0; j < 8; j++) bias_r[j] = bias[bcol * GBN + tn + j];
#pragma unroll
    for (int i = 0; i < 8; i++) {
        float4 v0 = make_float4(acc[i][0] + bias_r[0], acc[i][1] + bias_r[1],
                                acc[i][2] + bias_r[2], acc[i][3] + bias_r[3]);
        float4 v1 = make_float4(acc[i][4] + bias_r[4], acc[i][5] + bias_r[5],
                                acc[i][6] + bias_r[6], acc[i][7] + bias_r[7]);
        size_t row = (size_t)(brow * GBM + tm + i) * N + bcol * GBN + tn;
        *(float4*)&C[row]     = v0;
        *(float4*)&C[row + 4] = v1;
    }
}

// --------------------------- recurrence -------------------------------------
// CTA (n,g): tile = batch rows [g*8,g*8+8) x cols [n*32,n*32+32), K=1024.
// Usct[c][k] = Uh[k][n*32+c] (column-major slab, 129.5 KB in SMEM).
// Warp w: cols [w*4, w*4+4); lane: row = lane>>2, col = w*4 + (lane&3).
// Each lane: 1 output, 4 interleaved k-chains, full K -> no cross-warp reduce.
// Per step: lane0 polls cnt[t-1][g]==256, warp stages h row w (parity buffer),
// one __syncthreads, compute, tanh+STG, __syncwarp, lane0 red.release cnt[t][g].
__global__ void __launch_bounds__(256)
recur_kernel(float* __restrict__ out) {
    extern __shared__ float sm[];
    float* Usct = sm;                         // [32][UCT]
    float* hs   = sm + 32 * UCT;              // [2][8][HST] parity-buffered

    int tid = threadIdx.x;
    int n = blockIdx.x >> 2;                  // ntile 0..31
    int g = blockIdx.x & 3;                   // batch group 0..3
    int lane = tid & 31, w = tid >> 5;
    int r = lane >> 2;                        // row within group 0..7
    int c = (w << 2) + (lane & 3);            // col within tile 0..31

    size_t obase = (size_t)(g * 8 + r) * DD + n * 32 + c;

    // ---- t = 0: h0 = tanh(wh_out[0]); release ASAP, before Us load ----
    {
        float v0 = out[obase];
        out[obase] = tanhf(v0);
        __syncwarp();
        if (lane == 0) red_add_rel(&g_cnt[0][g], 1);
    }

    // ---- load + transpose Uh column slab: Usct[c][k] = Uh[k][n*32+c] ----
    for (int i = tid; i < 32 * 1024; i += 256) {
        int k = i >> 5, cc = i & 31;          // coalesced 128B reads per warp
        Usct[cc * UCT + k] = g_Uh[(size_t)k * DD + n * 32 + cc];
    }
    __syncthreads();

    const float* up = &Usct[c * UCT];

    for (int t = 1; t < TT; ++t) {
        // prefetch wh for this step (exclusively ours)
        float whv = __ldcg(&out[(size_t)t * BB * DD + obase]);

        if (lane == 0) spin_until(&g_cnt[t - 1][g], 256);
        __syncwarp();

        // warp w stages h row w into parity buffer
        float* hsp = &hs[(t & 1) * 8 * HST];
        {
            const float* hrow = out + (size_t)(t - 1) * BB * DD
                              + (size_t)(g * 8 + w) * DD;
            float* dst = &hsp[w * HST];
#pragma unroll
            for (int j = 0; j < 8; ++j) {
                float4 v = *(const float4*)&hrow[(lane << 2) + (j << 7)];
                *(float4*)&dst[(lane << 2) + (j << 7)] = v;
            }
        }
        __syncthreads();

        // full-K dot: 4 interleaved chains, LDS.128 streams on both operands
        const float* hp = &hsp[r * HST];
        float a0 = 0.f, a1 = 0.f, a2 = 0.f, a3 = 0.f;
#pragma unroll 8
        for (int kk = 0; kk < 1024; kk += 4) {
            float4 hv = *(const float4*)&hp[kk];
            float4 uv = *(const float4*)&up[kk];
            a0 += hv.x * uv.x;
            a1 += hv.y * uv.y;
            a2 += hv.z * uv.z;
            a3 += hv.w * uv.w;
        }
        float s = whv + ((a0 + a1) + (a2 + a3));
        out[(size_t)t * BB * DD + obase] = tanhf(s);

        __syncwarp();
        if (lane == 0) red_add_rel(&g_cnt[t][g], 1);
    }
}

// --------------------------- launch ------------------------------------------
extern "C" void kernel_launch(void* const* d_in, const int* in_sizes, int n_in,
                              void* d_out, int out_size) {
    const float* x    = (const float*)d_in[0];
    const float* wh_r = (const float*)d_in[1];
    const float* wh_i = (const float*)d_in[2];
    const float* wh_j = (const float*)d_in[3];
    const float* wh_k = (const float*)d_in[4];
    const float* uh_r = (const float*)d_in[5];
    const float* uh_i = (const float*)d_in[6];
    const float* uh_j = (const float*)d_in[7];
    const float* uh_k = (const float*)d_in[8];
    const float* wh_b = (const float*)d_in[9];
    float* out = (float*)d_out;

    zero_flags_kernel<<<(TT * 4 + 255) / 256, 256>>>();

    dim3 bq(DD / 256, DD);
    build_qmat_kernel<<<bq, 256>>>(wh_r, wh_i, wh_j, wh_k, 0);
    build_qmat_kernel<<<bq, 256>>>(uh_r, uh_i, uh_j, uh_k, 1);

    dim3 gg(DD / GBN, (TT * BB) / GBM);   // (8, 128)
    sgemm_bias_kernel<<<gg, 256>>>(x, wh_b, out, TT * BB, DD, DD);

    const int smem_bytes = (32 * UCT + 2 * 8 * HST) * 4;   // ~198 KB
    cudaFuncSetAttribute(recur_kernel,
                         cudaFuncAttributeMaxDynamicSharedMemorySize, smem_bytes);
    recur_kernel<<<32 * 4, 256, smem_bytes>>>(out);
}

// round 6
// speedup vs baseline: 1.6233x; 1.6233x over previous
#include <cuda_runtime.h>
#include <math.h>

// ---------------------------------------------------------------------------
// QRNN: h_t = tanh(x_t @ Wh + b + h_{t-1} @ Uh),  T=512, B=32, D=1024
// Phase B: fp32 SGEMM (R3-proven).
// Phase C: R3 recurrence topology (128 CTAs = 32 ntiles x 4 batch groups,
//          full-K per CTA, warp-split-K, SMEM reduce) with contention-free
//          per-CTA release flags instead of a shared atomic counter.
// ---------------------------------------------------------------------------

#define TT 512
#define BB 32
#define DD 1024
#define QQ 256

#define HS_STRIDE 1036
#define PART_STRIDE 264

__device__ float g_Wh[DD * DD];
__device__ float g_Uh[DD * DD];
__device__ int   g_done[TT][4][32];   // per (t, batch-group, ntile) flag

// ------------------------- sync primitives ----------------------------------
__device__ __forceinline__ int ld_acq(const int* p) {
    int v;
    asm volatile("ld.acquire.gpu.global.s32 %0, [%1];" : "=r"(v) : "l"(p) : "memory");
    return v;
}
__device__ __forceinline__ void st_rel(int* p, int v) {
    asm volatile("st.release.gpu.global.s32 [%0], %1;" :: "l"(p), "r"(v) : "memory");
}

// --------------------------- flag reset -------------------------------------
__global__ void zero_flags_kernel() {
    int i = blockIdx.x * blockDim.x + threadIdx.x;
    if (i < TT * 4 * 32) (&g_done[0][0][0])[i] = 0;
}

// --------------------------- quaternion matrix build ------------------------
__global__ void build_qmat_kernel(const float* __restrict__ wr,
                                  const float* __restrict__ wi,
                                  const float* __restrict__ wj,
                                  const float* __restrict__ wk,
                                  int which) {
    int e = blockIdx.x * blockDim.x + threadIdx.x;
    int d = blockIdx.y;
    int br = d >> 8, bc = e >> 8;
    int r = d & 255, c = e & 255;
    int comp = br ^ bc;
    int mask = (0x5390 >> (br * 4)) & 0xF;
    float s = ((mask >> bc) & 1) ? -1.0f : 1.0f;
    const float* w = (comp == 0) ? wr : (comp == 1) ? wi : (comp == 2) ? wj : wk;
    float* W = which ? g_Uh : g_Wh;
    W[d * DD + e] = s * w[r * QQ + c];
}

// --------------------------- fp32 SGEMM (R3 version) ------------------------
#define GBM 128
#define GBN 128
#define GBK 8

__global__ void __launch_bounds__(256)
sgemm_bias_kernel(const float* __restrict__ A, const float* __restrict__ bias,
                  float* __restrict__ C, int M, int N, int K) {
    __shared__ float As[2][GBK][GBM];
    __shared__ float Bs[2][GBK][GBN];
    const float* Bmat = g_Wh;

    int tid  = threadIdx.x;
    int brow = blockIdx.y, bcol = blockIdx.x;
    int arow = tid >> 1,  acol = (tid & 1) << 2;
    int brl  = tid >> 5,  bcl  = (tid & 31) << 2;

    const float* Ab = A + (size_t)(brow * GBM) * K;
    const float* Bb = Bmat + bcol * GBN;

    float4 av = *(const float4*)&Ab[(size_t)arow * K + acol];
    float4 bv = *(const float4*)&Bb[(size_t)brl * N + bcl];
    As[0][acol + 0][arow] = av.x;
    As[0][acol + 1][arow] = av.y;
    As[0][acol + 2][arow] = av.z;
    As[0][acol + 3][arow] = av.w;
    *(float4*)&Bs[0][brl][bcl] = bv;
    __syncthreads();

    int tm = (tid >> 4) << 3;
    int tn = (tid & 15) << 3;
    float acc[8][8];
#pragma unroll
    for (int i = 0; i < 8; i++)
#pragma unroll
        for (int j = 0; j < 8; j++) acc[i][j] = 0.0f;

    int nk = K / GBK;
    for (int kt = 0; kt < nk; ++kt) {
        int cur = kt & 1;
        float4 an, bn;
        if (kt + 1 < nk) {
            an = *(const float4*)&Ab[(size_t)arow * K + (kt + 1) * GBK + acol];
            bn = *(const float4*)&Bb[(size_t)((kt + 1) * GBK + brl) * N + bcl];
        }
#pragma unroll
        for (int kk = 0; kk < GBK; kk++) {
            float ra[8], rb[8];
            *(float4*)&ra[0] = *(const float4*)&As[cur][kk][tm];
            *(float4*)&ra[4] = *(const float4*)&As[cur][kk][tm + 4];
            *(float4*)&rb[0] = *(const float4*)&Bs[cur][kk][tn];
            *(float4*)&rb[4] = *(const float4*)&Bs[cur][kk][tn + 4];
#pragma unroll
            for (int i = 0; i < 8; i++)
#pragma unroll
                for (int j = 0; j < 8; j++) acc[i][j] += ra[i] * rb[j];
        }
        if (kt + 1 < nk) {
            int nxt = cur ^ 1;
            As[nxt][acol + 0][arow] = an.x;
            As[nxt][acol + 1][arow] = an.y;
            As[nxt][acol + 2][arow] = an.z;
            As[nxt][acol + 3][arow] = an.w;
            *(float4*)&Bs[nxt][brl][bcl] = bn;
            __syncthreads();
        }
    }

    float bias_r[8];
#pragma unroll
    for (int j = 0; j < 8; j++) bias_r[j] = bias[bcol * GBN + tn + j];
#pragma unroll
    for (int i = 0; i < 8; i++) {
        float4 v0 = make_float4(acc[i][0] + bias_r[0], acc[i][1] + bias_r[1],
                                acc[i][2] + bias_r[2], acc[i][3] + bias_r[3]);
        float4 v1 = make_float4(acc[i][4] + bias_r[4], acc[i][5] + bias_r[5],
                                acc[i][6] + bias_r[6], acc[i][7] + bias_r[7]);
        size_t row = (size_t)(brow * GBM + tm + i) * N + bcol * GBN + tn;
        *(float4*)&C[row]     = v0;
        *(float4*)&C[row + 4] = v1;
    }
}

// --------------------------- recurrence -------------------------------------
// CTA (n, g): output tile = batch rows [g*8, g*8+8) x cols [n*32, n*32+32),
// full K=1024. Uh[:, n*32..n*32+32) resident in SMEM (128 KB).
// 8 warps split K (128 each), register partials, SMEM reduce, tanh, STG,
// st.release own flag. Consumer polls its 32 producer flags in parallel
// (warp 0, one lane per flag) -- no atomic contention anywhere.
__global__ void __launch_bounds__(256)
recur_kernel(float* __restrict__ out) {
    extern __shared__ float sm[];
    float* Us   = sm;                          // [1024][32]
    float* hs   = Us + 1024 * 32;              // [8][HS_STRIDE]
    float* part = hs + 8 * HS_STRIDE;          // [8][PART_STRIDE]

    int tid = threadIdx.x;
    int n = blockIdx.x >> 2;                   // 0..31 ntile
    int g = blockIdx.x & 3;                    // 0..3 batch group

    // load Uh column slab: Us[k][c] = Uh[k][n*32+c]
    for (int i = tid; i < 1024 * 8; i += 256) {
        int k = i >> 3, c4 = (i & 7) << 2;
        *(float4*)&Us[k * 32 + c4] =
            *(const float4*)&g_Uh[(size_t)k * DD + n * 32 + c4];
    }

    int ob = tid >> 5, oc = tid & 31;          // this thread's output element
    size_t obase = (size_t)(g * 8 + ob) * DD + n * 32 + oc;

    // t = 0: h0 = tanh(wh_out[0])
    float v0 = out[obase];
    __syncthreads();                           // Us loaded
    out[obase] = tanhf(v0);
    __syncthreads();
    if (tid == 0) { __threadfence(); st_rel(&g_done[0][g][n], 1); }

    int lane = tid & 31, w = tid >> 5;
    int bg = (lane >> 3) << 1;                 // 0,2,4,6 : 2 batch rows
    int cg = (lane & 7) << 2;                  // 0..28   : 4 cols
    const int kbase = w << 7;                  // warp's K slice

    for (int t = 1; t < TT; ++t) {
        // prefetch wh for this step (exclusively ours) before the wait
        float whv = __ldcg(&out[(size_t)t * BB * DD + obase]);

        // parallel poll: warp 0's 32 lanes each watch one producer flag
        if (w == 0) {
            const int* fp = &g_done[t - 1][g][lane];
            int rdy = (ld_acq(fp) != 0);
            while (!__all_sync(0xffffffffu, rdy)) {
                if (!rdy) rdy = (ld_acq(fp) != 0);
            }
        }
        __syncthreads();

        // stage h_{t-1} rows of this batch group: 8 x 1024
        const float* hrow = out + (size_t)(t - 1) * BB * DD + (size_t)(g * 8) * DD;
        for (int i = tid; i < 2048; i += 256) {        // float4 granularity
            int b = i >> 8, k4 = (i & 255) << 2;
            *(float4*)&hs[b * HS_STRIDE + k4] =
                *(const float4*)&hrow[(size_t)b * DD + k4];
        }
        __syncthreads();

        float a0[4] = {0.f, 0.f, 0.f, 0.f};
        float a1[4] = {0.f, 0.f, 0.f, 0.f};
        const float* h0p = &hs[bg * HS_STRIDE + kbase];
        const float* h1p = &hs[(bg + 1) * HS_STRIDE + kbase];
        const float* up  = &Us[kbase * 32 + cg];

#pragma unroll 4
        for (int kk = 0; kk < 128; kk += 4) {
            float h0v[4], h1v[4];
            *(float4*)h0v = *(const float4*)&h0p[kk];
            *(float4*)h1v = *(const float4*)&h1p[kk];
#pragma unroll
            for (int q = 0; q < 4; q++) {
                float uv[4];
                *(float4*)uv = *(const float4*)&up[(kk + q) * 32];
#pragma unroll
                for (int j = 0; j < 4; j++) {
                    a0[j] += h0v[q] * uv[j];
                    a1[j] += h1v[q] * uv[j];
                }
            }
        }

        // intra-CTA split-K reduce through SMEM (fixed order => deterministic)
        *(float4*)&part[w * PART_STRIDE + bg * 32 + cg]       = *(float4*)a0;
        *(float4*)&part[w * PART_STRIDE + (bg + 1) * 32 + cg] = *(float4*)a1;
        __syncthreads();

        float s = whv;
#pragma unroll
        for (int ww = 0; ww < 8; ww++) s += part[ww * PART_STRIDE + tid];
        out[(size_t)t * BB * DD + obase] = tanhf(s);

        __syncthreads();                       // all STGs issued
        if (tid == 0) { __threadfence(); st_rel(&g_done[t][g][n], 1); }
    }
}

// --------------------------- launch ------------------------------------------
extern "C" void kernel_launch(void* const* d_in, const int* in_sizes, int n_in,
                              void* d_out, int out_size) {
    const float* x    = (const float*)d_in[0];
    const float* wh_r = (const float*)d_in[1];
    const float* wh_i = (const float*)d_in[2];
    const float* wh_j = (const float*)d_in[3];
    const float* wh_k = (const float*)d_in[4];
    const float* uh_r = (const float*)d_in[5];
    const float* uh_i = (const float*)d_in[6];
    const float* uh_j = (const float*)d_in[7];
    const float* uh_k = (const float*)d_in[8];
    const float* wh_b = (const float*)d_in[9];
    float* out = (float*)d_out;

    zero_flags_kernel<<<(TT * 4 * 32 + 255) / 256, 256>>>();

    dim3 bq(DD / 256, DD);
    build_qmat_kernel<<<bq, 256>>>(wh_r, wh_i, wh_j, wh_k, 0);
    build_qmat_kernel<<<bq, 256>>>(uh_r, uh_i, uh_j, uh_k, 1);

    dim3 gg(DD / GBN, (TT * BB) / GBM);   // (8, 128)
    sgemm_bias_kernel<<<gg, 256>>>(x, wh_b, out, TT * BB, DD, DD);

    const int smem_bytes = (1024 * 32 + 8 * HS_STRIDE + 8 * PART_STRIDE) * 4;
    cudaFuncSetAttribute(recur_kernel,
                         cudaFuncAttributeMaxDynamicSharedMemorySize, smem_bytes);
    recur_kernel<<<32 * 4, 256, smem_bytes>>>(out);
}